// round 16
// baseline (speedup 1.0000x reference)
#include <cuda_runtime.h>
#include <cuda_fp16.h>
#include <math.h>

#define NMAX 100000
#define EMAX 3200000
#define INC  256
#define HIDC 128
#define OUTC 2

typedef unsigned long long u64;

// ---------------- scratch (static device globals; no allocs) ----------------
__device__ __align__(256) u64   g_packed[NMAX];     // (cnt<<40) | fixed-point sum(w)
__device__ __align__(256) float g_deg[NMAX];        // dinv
__device__ __align__(256) int   g_fill[NMAX];       // absolute CSR cursors
__device__ __align__(256) int   g_rowptr[NMAX + 1];
__device__ __align__(256) int   g_bsum[128];
__device__ __align__(256) u64   g_edge[EMAX];       // (pnorm_bits<<32) | src ; pnorm = dinv[src]*w
__device__ __align__(256) __half g_h[NMAX * HIDC];  // x @ W1, fp16 storage
__device__ __align__(256) float g_t [NMAX * OUTC];
__device__ __align__(256) __half g_W1h[HIDC * INC]; // fp16 W1, [n][k]
__device__ int g_stride2;

#define WFIX 268435456.0f   // 2^28

// ---------------- fp16 mma helper ----------------
__device__ __forceinline__ void mma_f16(float c[4], const unsigned a[4],
                                        const unsigned b[2]) {
    asm("mma.sync.aligned.m16n8k16.row.col.f32.f16.f16.f32 "
        "{%0,%1,%2,%3}, {%4,%5,%6,%7}, {%8,%9}, {%0,%1,%2,%3};"
        : "+f"(c[0]), "+f"(c[1]), "+f"(c[2]), "+f"(c[3])
        : "r"(a[0]), "r"(a[1]), "r"(a[2]), "r"(a[3]), "r"(b[0]), "r"(b[1]));
}

__device__ __forceinline__ u64 pack_edge(int src, float nm) {
    return ((u64)__float_as_uint(nm) << 32) | (unsigned)src;
}
__device__ __forceinline__ void unpack_edge(u64 p, int& src, float& nm) {
    src = (int)(unsigned)p;
    nm = __uint_as_float((unsigned)(p >> 32));
}

// ---------------- layout detection (1 block) ----------------
__global__ void __launch_bounds__(256) k_detect(const int* __restrict__ ei) {
    __shared__ int s_or;
    if (threadIdx.x == 0) s_or = 0;
    __syncthreads();
    int acc = 0;
    for (int i = threadIdx.x; i < 4096; i += 256)
        acc |= ei[2 * i + 1];
    if (acc) atomicOr(&s_or, 1);
    __syncthreads();
    if (threadIdx.x == 0) g_stride2 = (s_or == 0) ? 1 : 0;
}

// ---------------- W1 -> fp16, transposed to [n][k] ----------------
__global__ void k_wconv(const float* __restrict__ W1) {
    int i = blockIdx.x * blockDim.x + threadIdx.x;
    if (i < INC * HIDC) {
        int k = i >> 7;
        int nn = i & 127;
        g_W1h[nn * INC + k] = __float2half_rn(W1[i]);
    }
}

// ---------------- edge pass 1: 4 edges/thread, one u64 atomic per edge -----
__global__ void k_edge1(const int* __restrict__ ei, const float* __restrict__ w,
                        int e, int n) {
    int t = blockIdx.x * blockDim.x + threadIdx.x;
    int i0 = 4 * t;
    if (i0 >= e) return;
    int st2 = g_stride2;
    int d0, d1, d2, d3;
    if (st2) {
        int4 a = *(const int4*)&ei[2 * e + 8 * t];
        int4 b = *(const int4*)&ei[2 * e + 8 * t + 4];
        d0 = a.x; d1 = a.z; d2 = b.x; d3 = b.z;
    } else {
        int4 a = *(const int4*)&ei[e + 4 * t];
        d0 = a.x; d1 = a.y; d2 = a.z; d3 = a.w;
    }
    float4 ww = *(const float4*)&w[i0];
    if ((unsigned)d0 < (unsigned)n)
        atomicAdd(&g_packed[d0], (1ULL << 40) | (u64)(ww.x * WFIX));
    if (i0 + 1 < e && (unsigned)d1 < (unsigned)n)
        atomicAdd(&g_packed[d1], (1ULL << 40) | (u64)(ww.y * WFIX));
    if (i0 + 2 < e && (unsigned)d2 < (unsigned)n)
        atomicAdd(&g_packed[d2], (1ULL << 40) | (u64)(ww.z * WFIX));
    if (i0 + 3 < e && (unsigned)d3 < (unsigned)n)
        atomicAdd(&g_packed[d3], (1ULL << 40) | (u64)(ww.w * WFIX));
}

// ---------------- scan1: warp-shuffle scan (+ dinv decode) -----------------
__global__ void __launch_bounds__(1024) k_scan1(int n) {
    __shared__ int s_w[32];
    int tid = threadIdx.x;
    int lane = tid & 31, wid = tid >> 5;
    int i = blockIdx.x * 1024 + tid;
    int v = 0;
    if (i < n) {
        u64 p = g_packed[i];
        v = (int)(p >> 40);
        float sumw = (float)(p & 0xFFFFFFFFFFULL) * (1.0f / WFIX);
        g_deg[i] = rsqrtf(sumw + 1.0f);      // +1 self-loop
    }
    int incl = v;
    #pragma unroll
    for (int off = 1; off < 32; off <<= 1) {
        int t = __shfl_up_sync(0xffffffffu, incl, off);
        if (lane >= off) incl += t;
    }
    if (lane == 31) s_w[wid] = incl;
    __syncthreads();
    if (wid == 0) {
        int ws = s_w[lane];
        #pragma unroll
        for (int off = 1; off < 32; off <<= 1) {
            int t = __shfl_up_sync(0xffffffffu, ws, off);
            if (lane >= off) ws += t;
        }
        s_w[lane] = ws;
    }
    __syncthreads();
    if (wid > 0) incl += s_w[wid - 1];
    if (i < n) g_rowptr[i] = incl - v;
    if (tid == 1023) g_bsum[blockIdx.x] = incl;
}

// ---------------- scan2+3 fused; seeds g_fill with absolute start ----------
__global__ void __launch_bounds__(1024) k_scan23(int n, int e, int nb) {
    __shared__ int s_off[32];
    int tid = threadIdx.x;
    int bid = blockIdx.x;
    int part = 0;
    if (tid < 128 && tid < bid && tid < nb) part = g_bsum[tid];
    if (tid < 128) {
        #pragma unroll
        for (int off = 16; off; off >>= 1)
            part += __shfl_xor_sync(0xffffffffu, part, off);
        if ((tid & 31) == 0) s_off[tid >> 5] = part;
    }
    __syncthreads();
    int offset = s_off[0] + s_off[1] + s_off[2] + s_off[3];
    int i = bid * 1024 + tid;
    if (i < n) {
        int r = g_rowptr[i] + offset;
        g_rowptr[i] = r;
        g_fill[i] = r;
    }
    if (i == 0) g_rowptr[n] = e;
}

// ---------------- edge pass 2: partial norm (no dst gather) ----------------
__global__ void k_edge2(const int* __restrict__ ei, const float* __restrict__ w,
                        int e, int n) {
    int t = blockIdx.x * blockDim.x + threadIdx.x;
    int i0 = 4 * t;
    if (i0 >= e) return;
    int st2 = g_stride2;
    int s0, s1, s2, s3, d0, d1, d2, d3;
    if (st2) {
        int4 sa = *(const int4*)&ei[8 * t];
        int4 sb = *(const int4*)&ei[8 * t + 4];
        int4 da = *(const int4*)&ei[2 * e + 8 * t];
        int4 db = *(const int4*)&ei[2 * e + 8 * t + 4];
        s0 = sa.x; s1 = sa.z; s2 = sb.x; s3 = sb.z;
        d0 = da.x; d1 = da.z; d2 = db.x; d3 = db.z;
    } else {
        int4 sa = *(const int4*)&ei[4 * t];
        int4 da = *(const int4*)&ei[e + 4 * t];
        s0 = sa.x; s1 = sa.y; s2 = sa.z; s3 = sa.w;
        d0 = da.x; d1 = da.y; d2 = da.z; d3 = da.w;
    }
    float4 ww = *(const float4*)&w[i0];
    if ((unsigned)s0 < (unsigned)n && (unsigned)d0 < (unsigned)n) {
        int pos = atomicAdd(&g_fill[d0], 1);
        if ((unsigned)pos < (unsigned)e)
            g_edge[pos] = pack_edge(s0, g_deg[s0] * ww.x);
    }
    if (i0 + 1 < e && (unsigned)s1 < (unsigned)n && (unsigned)d1 < (unsigned)n) {
        int pos = atomicAdd(&g_fill[d1], 1);
        if ((unsigned)pos < (unsigned)e)
            g_edge[pos] = pack_edge(s1, g_deg[s1] * ww.y);
    }
    if (i0 + 2 < e && (unsigned)s2 < (unsigned)n && (unsigned)d2 < (unsigned)n) {
        int pos = atomicAdd(&g_fill[d2], 1);
        if ((unsigned)pos < (unsigned)e)
            g_edge[pos] = pack_edge(s2, g_deg[s2] * ww.z);
    }
    if (i0 + 3 < e && (unsigned)s3 < (unsigned)n && (unsigned)d3 < (unsigned)n) {
        int pos = atomicAdd(&g_fill[d3], 1);
        if ((unsigned)pos < (unsigned)e)
            g_edge[pos] = pack_edge(s3, g_deg[s3] * ww.w);
    }
}

// ---------------- GEMM1: h = x @ W1 via fp16 m16n8k16 mma ------------------
#define ASTRD 36
#define BSTRD 132
#define GEMM1_SMEM ((2 * 128 * ASTRD + 128 * BSTRD) * 4)
extern __shared__ unsigned smem_g1[];

__device__ __forceinline__ void fill_A(unsigned* Ab, const float* __restrict__ x,
                                       int row0, int kc, int n, int tid) {
    #pragma unroll
    for (int t = 0; t < 8; t++) {
        int f = tid + t * 256;
        int r = f >> 4;
        int q = f & 15;
        int grow = row0 + r;
        float4 v = make_float4(0.f, 0.f, 0.f, 0.f);
        if (grow < n) v = *(const float4*)&x[grow * INC + kc * 64 + q * 4];
        __half2 p0 = __floats2half2_rn(v.x, v.y);
        __half2 p1 = __floats2half2_rn(v.z, v.w);
        uint2 st;
        st.x = *(unsigned*)&p0;
        st.y = *(unsigned*)&p1;
        *(uint2*)&Ab[r * ASTRD + q * 2] = st;
    }
}

__global__ void __launch_bounds__(256, 2) k_gemm1(const float* __restrict__ x,
                                                  int n) {
    unsigned* A0 = smem_g1;
    unsigned* A1 = A0 + 128 * ASTRD;
    unsigned* Bs = A1 + 128 * ASTRD;

    int tid = threadIdx.x;
    int wid = tid >> 5;
    int lane = tid & 31;
    int gr = lane >> 2;
    int gc = lane & 3;
    int wm = wid >> 2;
    int wn = wid & 3;
    int row0 = blockIdx.x * 128;

    #pragma unroll
    for (int t = 0; t < 16; t++) {
        int f = tid + t * 256;
        int col = f >> 5;
        int q4 = f & 31;
        *(uint4*)&Bs[col * BSTRD + q4 * 4] =
            *(const uint4*)&g_W1h[col * INC + q4 * 8];
    }
    fill_A(A0, x, row0, 0, n, tid);
    __syncthreads();

    float c[4][4][4];
    #pragma unroll
    for (int mt = 0; mt < 4; mt++)
        #pragma unroll
        for (int nt = 0; nt < 4; nt++)
            #pragma unroll
            for (int q = 0; q < 4; q++) c[mt][nt][q] = 0.f;

    #pragma unroll
    for (int kc = 0; kc < INC / 64; kc++) {
        unsigned* Ac = (kc & 1) ? A1 : A0;
        unsigned* An = (kc & 1) ? A0 : A1;
        if (kc < INC / 64 - 1)
            fill_A(An, x, row0, kc + 1, n, tid);

        #pragma unroll
        for (int ks = 0; ks < 4; ks++) {
            int kp = ks * 8;
            unsigned a[4][4], b[4][2];
            #pragma unroll
            for (int mt = 0; mt < 4; mt++) {
                int r = wm * 64 + mt * 16 + gr;
                a[mt][0] = Ac[r * ASTRD + kp + gc];
                a[mt][1] = Ac[(r + 8) * ASTRD + kp + gc];
                a[mt][2] = Ac[r * ASTRD + kp + gc + 4];
                a[mt][3] = Ac[(r + 8) * ASTRD + kp + gc + 4];
            }
            #pragma unroll
            for (int nt = 0; nt < 4; nt++) {
                int col = wn * 32 + nt * 8 + gr;
                b[nt][0] = Bs[col * BSTRD + kc * 32 + kp + gc];
                b[nt][1] = Bs[col * BSTRD + kc * 32 + kp + gc + 4];
            }
            #pragma unroll
            for (int mt = 0; mt < 4; mt++)
                #pragma unroll
                for (int nt = 0; nt < 4; nt++)
                    mma_f16(c[mt][nt], a[mt], b[nt]);
        }
        __syncthreads();
    }

    #pragma unroll
    for (int mt = 0; mt < 4; mt++) {
        int r0 = row0 + wm * 64 + mt * 16 + gr;
        #pragma unroll
        for (int nt = 0; nt < 4; nt++) {
            int cc = wn * 32 + nt * 8 + 2 * gc;
            if (r0 < n)
                *(__half2*)&g_h[r0 * HIDC + cc] =
                    __floats2half2_rn(c[mt][nt][0], c[mt][nt][1]);
            if (r0 + 8 < n)
                *(__half2*)&g_h[(r0 + 8) * HIDC + cc] =
                    __floats2half2_rn(c[mt][nt][2], c[mt][nt][3]);
        }
    }
}

// ---------------- agg1 (+ fused relu/bias + GEMM2): warp per node ----------
__device__ __forceinline__ void agg_edge(float4& acc, const uint2* hp, u64 p,
                                         int lane) {
    int s; float nm;
    unpack_edge(p, s, nm);
    uint2 u = hp[s * 32 + lane];
    float2 a0 = __half22float2(*(__half2*)&u.x);
    float2 a1 = __half22float2(*(__half2*)&u.y);
    acc.x += nm * a0.x; acc.y += nm * a0.y;
    acc.z += nm * a1.x; acc.w += nm * a1.y;
}

__global__ void __launch_bounds__(256) k_agg1(const float* __restrict__ b1,
                                              const float* __restrict__ W2, int n) {
    __shared__ float w2s[HIDC * OUTC];
    if (threadIdx.x < HIDC * OUTC) w2s[threadIdx.x] = W2[threadIdx.x];
    __syncthreads();

    int warp = (blockIdx.x * blockDim.x + threadIdx.x) >> 5;
    int lane = threadIdx.x & 31;
    if (warp >= n) return;
    const uint2* hp = (const uint2*)g_h;

    float4 acc = make_float4(0.f, 0.f, 0.f, 0.f);

    int beg = g_rowptr[warp], end = g_rowptr[warp + 1];
    int j = beg;
    int alignEnd = (beg + 3) & ~3;
    if (alignEnd > end) alignEnd = end;
    for (; j < alignEnd; j++)
        agg_edge(acc, hp, g_edge[j], lane);
    for (; j + 3 < end; j += 4) {
        ulonglong2 p01 = *(const ulonglong2*)&g_edge[j];
        ulonglong2 p23 = *(const ulonglong2*)&g_edge[j + 2];
        int s0, s1, s2, s3; float n0, n1, n2, n3;
        unpack_edge(p01.x, s0, n0);
        unpack_edge(p01.y, s1, n1);
        unpack_edge(p23.x, s2, n2);
        unpack_edge(p23.y, s3, n3);
        uint2 u0 = hp[s0 * 32 + lane];
        uint2 u1 = hp[s1 * 32 + lane];
        uint2 u2 = hp[s2 * 32 + lane];
        uint2 u3 = hp[s3 * 32 + lane];
        float2 a0 = __half22float2(*(__half2*)&u0.x);
        float2 a1 = __half22float2(*(__half2*)&u0.y);
        float2 b0 = __half22float2(*(__half2*)&u1.x);
        float2 b1v = __half22float2(*(__half2*)&u1.y);
        float2 c0 = __half22float2(*(__half2*)&u2.x);
        float2 c1 = __half22float2(*(__half2*)&u2.y);
        float2 d0 = __half22float2(*(__half2*)&u3.x);
        float2 d1 = __half22float2(*(__half2*)&u3.y);
        acc.x += n0 * a0.x + n1 * b0.x + n2 * c0.x + n3 * d0.x;
        acc.y += n0 * a0.y + n1 * b0.y + n2 * c0.y + n3 * d0.y;
        acc.z += n0 * a1.x + n1 * b1v.x + n2 * c1.x + n3 * d1.x;
        acc.w += n0 * a1.y + n1 * b1v.y + n2 * c1.y + n3 * d1.y;
    }
    for (; j < end; j++)
        agg_edge(acc, hp, g_edge[j], lane);

    float din = g_deg[warp];
    float sl = din * din;
    uint2 us = hp[warp * 32 + lane];
    float2 f0 = __half22float2(*(__half2*)&us.x);
    float2 f1 = __half22float2(*(__half2*)&us.y);

    float4 o;
    o.x = fmaxf(din * acc.x + sl * f0.x + b1[lane * 4 + 0], 0.f);
    o.y = fmaxf(din * acc.y + sl * f0.y + b1[lane * 4 + 1], 0.f);
    o.z = fmaxf(din * acc.z + sl * f1.x + b1[lane * 4 + 2], 0.f);
    o.w = fmaxf(din * acc.w + sl * f1.y + b1[lane * 4 + 3], 0.f);

    int k = lane * 4;
    float ax = o.x * w2s[(k + 0) * 2]     + o.y * w2s[(k + 1) * 2]
             + o.z * w2s[(k + 2) * 2]     + o.w * w2s[(k + 3) * 2];
    float ay = o.x * w2s[(k + 0) * 2 + 1] + o.y * w2s[(k + 1) * 2 + 1]
             + o.z * w2s[(k + 2) * 2 + 1] + o.w * w2s[(k + 3) * 2 + 1];
    #pragma unroll
    for (int off = 16; off; off >>= 1) {
        ax += __shfl_xor_sync(0xffffffffu, ax, off);
        ay += __shfl_xor_sync(0xffffffffu, ay, off);
    }
    if (lane == 0) {
        g_t[2 * warp]     = ax;
        g_t[2 * warp + 1] = ay;
    }
}

// ---------------- agg2: warp per node, 2 edges/lane (16B loads) ------------
__global__ void k_agg2(const float* __restrict__ b2, float* __restrict__ out, int n) {
    int warp = (blockIdx.x * blockDim.x + threadIdx.x) >> 5;
    int lane = threadIdx.x & 31;
    if (warp >= n) return;
    const float2* tp = (const float2*)g_t;
    float ax = 0.f, ay = 0.f;
    int beg = g_rowptr[warp], end = g_rowptr[warp + 1];

    int j0 = beg;
    if ((beg & 1) && beg < end) {       // odd head: lane 0 handles it
        if (lane == 0) {
            int s; float nm;
            unpack_edge(g_edge[beg], s, nm);
            float2 v = tp[s];
            ax += nm * v.x; ay += nm * v.y;
        }
        j0 = beg + 1;
    }
    int npairs = (end - j0) >> 1;
    for (int p = lane; p < npairs; p += 32) {
        ulonglong2 pr = *(const ulonglong2*)&g_edge[j0 + 2 * p];
        int s0, s1; float n0, n1;
        unpack_edge(pr.x, s0, n0);
        unpack_edge(pr.y, s1, n1);
        float2 v0 = tp[s0];
        float2 v1 = tp[s1];
        ax += n0 * v0.x + n1 * v1.x;
        ay += n0 * v0.y + n1 * v1.y;
    }
    if (((end - j0) & 1) && end > j0) { // odd tail: lane 0
        if (lane == 0) {
            int s; float nm;
            unpack_edge(g_edge[end - 1], s, nm);
            float2 v = tp[s];
            ax += nm * v.x; ay += nm * v.y;
        }
    }

    #pragma unroll
    for (int off = 16; off; off >>= 1) {
        ax += __shfl_xor_sync(0xffffffffu, ax, off);
        ay += __shfl_xor_sync(0xffffffffu, ay, off);
    }
    if (lane == 0) {
        float din = g_deg[warp];
        float sl = din * din;
        float2 tv = tp[warp];
        out[2 * warp]     = din * ax + sl * tv.x + b2[0];
        out[2 * warp + 1] = din * ay + sl * tv.y + b2[1];
    }
}

// ---------------- launcher: CSR build overlapped with GEMM1 ----------------
extern "C" void kernel_launch(void* const* d_in, const int* in_sizes, int n_in,
                              void* d_out, int out_size) {
    const float* x  = nullptr; const int* ei = nullptr; const float* w  = nullptr;
    const float* W1 = nullptr; const float* b1 = nullptr;
    const float* W2 = nullptr; const float* b2 = nullptr;
    long long e = 0;
    for (int i = 0; i < n_in; i++) {
        long long s = in_sizes[i];
        if      (s == 25600000LL) { x  = (const float*)d_in[i]; }
        else if (s == 6400000LL || s == 12800000LL) { ei = (const int*)d_in[i]; }
        else if (s == 3200000LL)  { w  = (const float*)d_in[i]; e = s; }
        else if (s == 32768LL)    { W1 = (const float*)d_in[i]; }
        else if (s == 128LL)      { b1 = (const float*)d_in[i]; }
        else if (s == 256LL)      { W2 = (const float*)d_in[i]; }
        else if (s == 2LL)        { b2 = (const float*)d_in[i]; }
    }
    float* out = (float*)d_out;
    int ni = 100000, ee = (int)e;
    int nb1024 = (ni + 1023) / 1024;

    static cudaStream_t s_side = nullptr;
    static cudaEvent_t ev_fork = nullptr, ev_join = nullptr;
    static void* p_packed = nullptr;
    if (!s_side) {
        int prLo = 0, prHi = 0;
        cudaDeviceGetStreamPriorityRange(&prLo, &prHi);
        cudaStreamCreateWithPriority(&s_side, cudaStreamNonBlocking, prHi);
        cudaEventCreateWithFlags(&ev_fork, cudaEventDisableTiming);
        cudaEventCreateWithFlags(&ev_join, cudaEventDisableTiming);
        cudaFuncSetAttribute(k_gemm1, cudaFuncAttributeMaxDynamicSharedMemorySize,
                             GEMM1_SMEM);
        cudaGetSymbolAddress(&p_packed, g_packed);
    }

    cudaEventRecord(ev_fork, 0);
    cudaStreamWaitEvent(s_side, ev_fork, 0);

    cudaMemsetAsync(p_packed, 0, NMAX * sizeof(u64), s_side);
    k_detect<<<1, 256, 0, s_side>>>(ei);
    k_edge1 <<<(ee / 4 + 255) / 256, 256, 0, s_side>>>(ei, w, ee, ni);
    k_scan1 <<<nb1024, 1024, 0, s_side>>>(ni);
    k_scan23<<<nb1024, 1024, 0, s_side>>>(ni, ee, nb1024);
    k_edge2 <<<(ee / 4 + 255) / 256, 256, 0, s_side>>>(ei, w, ee, ni);
    cudaEventRecord(ev_join, s_side);

    k_wconv<<<(INC * HIDC + 255) / 256, 256>>>(W1);
    k_gemm1<<<(ni + 127) / 128, 256, GEMM1_SMEM>>>(x, ni);

    cudaStreamWaitEvent(0, ev_join, 0);

    k_agg1 <<<(ni + 7) / 8, 256>>>(b1, W2, ni);
    k_agg2 <<<(ni + 7) / 8, 256>>>(b2, out, ni);
}